// round 14
// baseline (speedup 1.0000x reference)
#include <cuda_runtime.h>

#define NVOX 500000
#define CH 8
#define KT 27
#define TPB 128
#define RPT 4                      // rows per thread
#define RPB (TPB * RPT)            // 512 rows per block
#define KCH 9                      // taps per smem chunk (3 chunks of 9)
#define HGRID ((NVOX + RPB - 1) / RPB)   // blocks per grid (977)

// Ping-pong scratch for intermediate activations, one pair per grid.
__device__ float g_bufA0[NVOX * CH];
__device__ float g_bufB0[NVOX * CH];
__device__ float g_bufA1[NVOX * CH];
__device__ float g_bufB1[NVOX * CH];

__device__ __forceinline__ void ffma2(unsigned long long& d,
                                      unsigned long long a,
                                      unsigned long long b) {
    asm volatile("fma.rn.f32x2 %0, %1, %2, %0;" : "+l"(d) : "l"(a), "l"(b));
}

__device__ __forceinline__ unsigned long long pack2(float x) {
    unsigned long long r;
    unsigned int xb = __float_as_uint(x);
    asm("mov.b64 %0, {%1, %1};" : "=l"(r) : "r"(xb));
    return r;
}

// 256-bit row load (sm_100+): one LDG fetches the full 8-float row.
__device__ __forceinline__ void ldg256(const float* p, float* f) {
    asm("ld.global.nc.L1::no_allocate.v8.f32 {%0,%1,%2,%3,%4,%5,%6,%7}, [%8];"
        : "=f"(f[0]), "=f"(f[1]), "=f"(f[2]), "=f"(f[3]),
          "=f"(f[4]), "=f"(f[5]), "=f"(f[6]), "=f"(f[7])
        : "l"(p));
}

__device__ __forceinline__ void stg256(float* p, const float* f) {
    asm volatile("st.global.v8.f32 [%0], {%1,%2,%3,%4,%5,%6,%7,%8};"
        :: "l"(p),
           "f"(f[0]), "f"(f[1]), "f"(f[2]), "f"(f[3]),
           "f"(f[4]), "f"(f[5]), "f"(f[6]), "f"(f[7])
        : "memory");
}

__device__ __forceinline__ void pref_l2(const float* p) {
    asm volatile("prefetch.global.L2 [%0];" :: "l"(p));
}

// One sparse-conv layer for one grid (R13-proven inner structure + L2 prefetch).
template <bool RELU, bool RES>
__global__ void __launch_bounds__(TPB, 5)
spconv_kernel(const float* __restrict__ x,
              const int*   __restrict__ nbr,
              const float* __restrict__ w,
              const float* __restrict__ resid,
              float*       __restrict__ out)
{
    // Weights as f32x2 pairs: sw[k*32 + cin*4 + p] = (w[k][cin][2p], w[k][cin][2p+1])
    __shared__ __align__(16) unsigned long long sw[KT * 32];   // 6912 B
    __shared__ __align__(16) int snbr[RPB * KCH];              // 18432 B

    {
        const unsigned long long* w2 = (const unsigned long long*)w;
        for (int i = threadIdx.x; i < KT * 32; i += TPB) sw[i] = w2[i];
    }

    const int t = threadIdx.x;
    const int base = blockIdx.x * RPB;
    const int rows = min(RPB, NVOX - base);

    int r[RPT]; bool ok[RPT];
#pragma unroll
    for (int s = 0; s < RPT; s++) {
        r[s] = base + t + TPB * s;
        ok[s] = (r[s] < NVOX);
    }

    unsigned long long acc[RPT][4];
#pragma unroll
    for (int s = 0; s < RPT; s++)
#pragma unroll
        for (int q = 0; q < 4; q++) acc[s][q] = 0ull;

    float D0[RPT][8], D1[RPT][8];
    int j[RPT], jp[RPT];

#define LOAD_DATA(J, D)                                          \
    {                                                            \
        _Pragma("unroll")                                        \
        for (int s = 0; s < RPT; s++) {                          \
            if (J[s] >= 0) {                                     \
                ldg256(x + (size_t)J[s] * 8, D[s]);              \
            } else {                                             \
                _Pragma("unroll")                                \
                for (int c = 0; c < 8; c++) D[s][c] = 0.f;       \
            }                                                    \
        }                                                        \
    }

#define LOAD_IDX(u, J)                                           \
    {                                                            \
        _Pragma("unroll")                                        \
        for (int s = 0; s < RPT; s++)                            \
            J[s] = ok[s] ? snbr[(t + TPB * s) * KCH + (u)] : -1; \
    }

// Pull tap (u)'s gather lines into L2 two taps early.
#define PREF_TAP(u)                                              \
    {                                                            \
        LOAD_IDX(u, jp);                                         \
        _Pragma("unroll")                                        \
        for (int s = 0; s < RPT; s++)                            \
            if (jp[s] >= 0) pref_l2(x + (size_t)jp[s] * 8);      \
    }

#define FMA_TAP(k, D)                                                       \
    {                                                                       \
        const unsigned long long* wk = sw + (k) * 32;                       \
        _Pragma("unroll")                                                   \
        for (int c = 0; c < 8; c++) {                                       \
            const ulonglong2 wA = *(const ulonglong2*)(wk + c * 4);         \
            const ulonglong2 wB = *(const ulonglong2*)(wk + c * 4 + 2);     \
            _Pragma("unroll")                                               \
            for (int s = 0; s < RPT; s++) {                                 \
                const unsigned long long p = pack2(D[s][c]);                \
                ffma2(acc[s][0], p, wA.x);                                  \
                ffma2(acc[s][1], p, wA.y);                                  \
                ffma2(acc[s][2], p, wB.x);                                  \
                ffma2(acc[s][3], p, wB.y);                                  \
            }                                                               \
        }                                                                   \
    }

    const int* src = nbr + (long long)base * KT;

#pragma unroll 1
    for (int g = 0; g < 3; g++) {
        const int kbase = g * KCH;
        __syncthreads();   // also covers weight staging on g==0
        {
            const int tot = rows * KCH;
            for (int i = t; i < tot; i += TPB) {
                const int row = i / KCH;
                const int kk = i - row * KCH;
                snbr[i] = src[row * KT + kbase + kk];
            }
        }
        __syncthreads();

        // 2-deep gather pipeline + L2 prefetch 2 taps ahead.
        LOAD_IDX(0, j);
        LOAD_DATA(j, D0);
#pragma unroll
        for (int u = 0; u < KCH - 1; u++) {
            LOAD_IDX(u + 1, j);
            if (u + 2 < KCH) PREF_TAP(u + 2);
            if (u & 1) {
                LOAD_DATA(j, D0);
                FMA_TAP(kbase + u, D1);
            } else {
                LOAD_DATA(j, D1);
                FMA_TAP(kbase + u, D0);
            }
        }
        FMA_TAP(kbase + KCH - 1, D0);   // tap 8 data sits in D0
    }

    // Epilogue
#pragma unroll
    for (int s = 0; s < RPT; s++) {
        if (!ok[s]) continue;
        float v[8];
#pragma unroll
        for (int i = 0; i < 4; i++) {
            unsigned int lo, hi;
            asm("mov.b64 {%0, %1}, %2;" : "=r"(lo), "=r"(hi) : "l"(acc[s][i]));
            v[2 * i]     = __uint_as_float(lo);
            v[2 * i + 1] = __uint_as_float(hi);
        }
        if (RES) {
            float ra[8];
            ldg256(resid + (size_t)r[s] * 8, ra);
#pragma unroll
            for (int i = 0; i < 8; i++) v[i] += ra[i];
        }
        if (RELU) {
#pragma unroll
            for (int i = 0; i < 8; i++) v[i] = fmaxf(v[i], 0.f);
        }
        stg256(out + (size_t)r[s] * 8, v);
    }
#undef LOAD_DATA
#undef LOAD_IDX
#undef PREF_TAP
#undef FMA_TAP
}

extern "C" void kernel_launch(void* const* d_in, const int* in_sizes, int n_in,
                              void* d_out, int out_size) {
    (void)in_sizes; (void)n_in; (void)out_size;
    const float* feats0 = (const float*)d_in[0];
    const float* feats1 = (const float*)d_in[1];
    const float* W0     = (const float*)d_in[2];  // [3][27][8][8]
    const float* W1     = (const float*)d_in[3];
    const int*   nbr0   = (const int*)d_in[4];    // [N][27]
    const int*   nbr1   = (const int*)d_in[5];
    float* out = (float*)d_out;

    float *bufA0, *bufB0, *bufA1, *bufB1;
    cudaGetSymbolAddress((void**)&bufA0, g_bufA0);
    cudaGetSymbolAddress((void**)&bufB0, g_bufB0);
    cudaGetSymbolAddress((void**)&bufA1, g_bufA1);
    cudaGetSymbolAddress((void**)&bufB1, g_bufB1);

    // Lazy host-side stream/event setup (no device memory involved).
    static cudaStream_t s1 = nullptr;
    static cudaEvent_t eFork = nullptr, eJoin = nullptr;
    if (s1 == nullptr) {
        cudaStreamCreateWithFlags(&s1, cudaStreamNonBlocking);
        cudaEventCreateWithFlags(&eFork, cudaEventDisableTiming);
        cudaEventCreateWithFlags(&eJoin, cudaEventDisableTiming);
    }

    const int LW = KT * CH * CH;  // 1728 floats per layer

    // Fork: s1 joins the captured (default) stream's dependency front.
    cudaEventRecord(eFork, 0);
    cudaStreamWaitEvent(s1, eFork, 0);

    // Chain for grid 0 on the default stream.
    spconv_kernel<true,  false><<<HGRID, TPB>>>(feats0, nbr0, W0,          nullptr, bufA0);
    spconv_kernel<true,  false><<<HGRID, TPB>>>(bufA0,  nbr0, W0 + LW,     nullptr, bufB0);
    spconv_kernel<false, true ><<<HGRID, TPB>>>(bufB0,  nbr0, W0 + 2 * LW, feats0,  out);

    // Chain for grid 1 on s1.
    spconv_kernel<true,  false><<<HGRID, TPB, 0, s1>>>(feats1, nbr1, W1,          nullptr, bufA1);
    spconv_kernel<true,  false><<<HGRID, TPB, 0, s1>>>(bufA1,  nbr1, W1 + LW,     nullptr, bufB1);
    spconv_kernel<false, true ><<<HGRID, TPB, 0, s1>>>(bufB1,  nbr1, W1 + 2 * LW, feats1,
                                                       out + (size_t)NVOX * CH);

    // Join: default stream waits for s1's chain.
    cudaEventRecord(eJoin, s1);
    cudaStreamWaitEvent(0, eJoin, 0);
}

// round 16
// speedup vs baseline: 1.2759x; 1.2759x over previous
#include <cuda_runtime.h>

#define NVOX 500000
#define CH 8
#define KT 27
#define TPB 128
#define RPT 4                      // rows per thread
#define RPB (TPB * RPT)            // 512 rows per block
#define KCH 9                      // taps per smem chunk (3 chunks of 9)
#define LW (KT * CH * CH)          // 1728 floats per layer
#define HGRID ((NVOX + RPB - 1) / RPB)   // blocks per grid (977)

// Ping-pong scratch for intermediate activations, one pair per grid.
__device__ float g_bufA0[NVOX * CH];
__device__ float g_bufB0[NVOX * CH];
__device__ float g_bufA1[NVOX * CH];
__device__ float g_bufB1[NVOX * CH];

// All 3 layers' weights for both grids in the constant bank (2*3*1728 floats
// = 41472 B < 64 KB). Filled per-capture by async D2D symbol copies.
__constant__ float c_W[2 * 3 * LW];

__device__ __forceinline__ void ffma2(unsigned long long& d,
                                      unsigned long long a,
                                      unsigned long long b) {
    asm volatile("fma.rn.f32x2 %0, %1, %2, %0;" : "+l"(d) : "l"(a), "l"(b));
}

__device__ __forceinline__ unsigned long long pack2(float x) {
    unsigned long long r;
    unsigned int xb = __float_as_uint(x);
    asm("mov.b64 %0, {%1, %1};" : "=l"(r) : "r"(xb));
    return r;
}

// 256-bit row load (sm_100+): one LDG fetches the full 8-float row.
__device__ __forceinline__ void ldg256(const float* p, float* f) {
    asm("ld.global.nc.v8.f32 {%0,%1,%2,%3,%4,%5,%6,%7}, [%8];"
        : "=f"(f[0]), "=f"(f[1]), "=f"(f[2]), "=f"(f[3]),
          "=f"(f[4]), "=f"(f[5]), "=f"(f[6]), "=f"(f[7])
        : "l"(p));
}

__device__ __forceinline__ void stg256(float* p, const float* f) {
    asm volatile("st.global.v8.f32 [%0], {%1,%2,%3,%4,%5,%6,%7,%8};"
        :: "l"(p),
           "f"(f[0]), "f"(f[1]), "f"(f[2]), "f"(f[3]),
           "f"(f[4]), "f"(f[5]), "f"(f[6]), "f"(f[7])
        : "memory");
}

// One sparse-conv layer for one grid. Weights read from the constant bank
// (warp-uniform -> constant port, off the L1tex path).
template <bool RELU, bool RES>
__global__ void __launch_bounds__(TPB, 5)
spconv_kernel(const float* __restrict__ x,
              const int*   __restrict__ nbr,
              int          wofs,             // float offset of this layer in c_W
              const float* __restrict__ resid,
              float*       __restrict__ out)
{
    __shared__ __align__(16) int snbr[RPB * KCH];              // 18432 B

    const int t = threadIdx.x;
    const int base = blockIdx.x * RPB;
    const int rows = min(RPB, NVOX - base);

    int r[RPT]; bool ok[RPT];
#pragma unroll
    for (int s = 0; s < RPT; s++) {
        r[s] = base + t + TPB * s;
        ok[s] = (r[s] < NVOX);
    }

    unsigned long long acc[RPT][4];
#pragma unroll
    for (int s = 0; s < RPT; s++)
#pragma unroll
        for (int q = 0; q < 4; q++) acc[s][q] = 0ull;

    float D0[RPT][8], D1[RPT][8];
    int j[RPT];

#define LOAD_DATA(J, D)                                          \
    {                                                            \
        _Pragma("unroll")                                        \
        for (int s = 0; s < RPT; s++) {                          \
            if (J[s] >= 0) {                                     \
                ldg256(x + (size_t)J[s] * 8, D[s]);              \
            } else {                                             \
                _Pragma("unroll")                                \
                for (int c = 0; c < 8; c++) D[s][c] = 0.f;       \
            }                                                    \
        }                                                        \
    }

#define LOAD_IDX(u, J)                                           \
    {                                                            \
        _Pragma("unroll")                                        \
        for (int s = 0; s < RPT; s++)                            \
            J[s] = ok[s] ? snbr[(t + TPB * s) * KCH + (u)] : -1; \
    }

// Weights w[k][c][0..7] are 8 consecutive floats in c_W; read them as two
// 16B constant-bank vectors (uniform address across the warp).
#define FMA_TAP(k, D)                                                       \
    {                                                                       \
        const float* wk = c_W + wofs + (k) * 64;                            \
        _Pragma("unroll")                                                   \
        for (int c = 0; c < 8; c++) {                                       \
            const ulonglong2 wA = *(const ulonglong2*)(wk + c * 8);         \
            const ulonglong2 wB = *(const ulonglong2*)(wk + c * 8 + 4);     \
            _Pragma("unroll")                                               \
            for (int s = 0; s < RPT; s++) {                                 \
                const unsigned long long p = pack2(D[s][c]);                \
                ffma2(acc[s][0], p, wA.x);                                  \
                ffma2(acc[s][1], p, wA.y);                                  \
                ffma2(acc[s][2], p, wB.x);                                  \
                ffma2(acc[s][3], p, wB.y);                                  \
            }                                                               \
        }                                                                   \
    }

    const int* src = nbr + (long long)base * KT;

#pragma unroll 1
    for (int g = 0; g < 3; g++) {
        const int kbase = g * KCH;
        __syncthreads();
        {
            const int tot = rows * KCH;
            for (int i = t; i < tot; i += TPB) {
                const int row = i / KCH;
                const int kk = i - row * KCH;
                snbr[i] = src[row * KT + kbase + kk];
            }
        }
        __syncthreads();

        // 2-deep gather pipeline over the 9 taps of this chunk.
        LOAD_IDX(0, j);
        LOAD_DATA(j, D0);
#pragma unroll
        for (int u = 0; u < KCH - 1; u++) {
            LOAD_IDX(u + 1, j);
            if (u & 1) {
                LOAD_DATA(j, D0);
                FMA_TAP(kbase + u, D1);
            } else {
                LOAD_DATA(j, D1);
                FMA_TAP(kbase + u, D0);
            }
        }
        FMA_TAP(kbase + KCH - 1, D0);   // tap 8 data sits in D0
    }

    // Epilogue
#pragma unroll
    for (int s = 0; s < RPT; s++) {
        if (!ok[s]) continue;
        float v[8];
#pragma unroll
        for (int i = 0; i < 4; i++) {
            unsigned int lo, hi;
            asm("mov.b64 {%0, %1}, %2;" : "=r"(lo), "=r"(hi) : "l"(acc[s][i]));
            v[2 * i]     = __uint_as_float(lo);
            v[2 * i + 1] = __uint_as_float(hi);
        }
        if (RES) {
            float ra[8];
            ldg256(resid + (size_t)r[s] * 8, ra);
#pragma unroll
            for (int i = 0; i < 8; i++) v[i] += ra[i];
        }
        if (RELU) {
#pragma unroll
            for (int i = 0; i < 8; i++) v[i] = fmaxf(v[i], 0.f);
        }
        stg256(out + (size_t)r[s] * 8, v);
    }
#undef LOAD_DATA
#undef LOAD_IDX
#undef FMA_TAP
}

extern "C" void kernel_launch(void* const* d_in, const int* in_sizes, int n_in,
                              void* d_out, int out_size) {
    (void)in_sizes; (void)n_in; (void)out_size;
    const float* feats0 = (const float*)d_in[0];
    const float* feats1 = (const float*)d_in[1];
    const float* W0     = (const float*)d_in[2];  // [3][27][8][8]
    const float* W1     = (const float*)d_in[3];
    const int*   nbr0   = (const int*)d_in[4];    // [N][27]
    const int*   nbr1   = (const int*)d_in[5];
    float* out = (float*)d_out;

    float *bufA0, *bufB0, *bufA1, *bufB1;
    cudaGetSymbolAddress((void**)&bufA0, g_bufA0);
    cudaGetSymbolAddress((void**)&bufB0, g_bufB0);
    cudaGetSymbolAddress((void**)&bufA1, g_bufA1);
    cudaGetSymbolAddress((void**)&bufB1, g_bufB1);

    // Lazy host-side stream/event setup (no device memory involved).
    static cudaStream_t s1 = nullptr;
    static cudaEvent_t eFork = nullptr, eJoin = nullptr;
    if (s1 == nullptr) {
        cudaStreamCreateWithFlags(&s1, cudaStreamNonBlocking);
        cudaEventCreateWithFlags(&eFork, cudaEventDisableTiming);
        cudaEventCreateWithFlags(&eJoin, cudaEventDisableTiming);
    }

    // Fork: s1 joins the captured (default) stream's dependency front.
    cudaEventRecord(eFork, 0);
    cudaStreamWaitEvent(s1, eFork, 0);

    // Stage weights into the constant bank (async D2D, graph-capturable).
    cudaMemcpyToSymbolAsync(c_W, W0, sizeof(float) * 3 * LW, 0,
                            cudaMemcpyDeviceToDevice, 0);
    cudaMemcpyToSymbolAsync(c_W, W1, sizeof(float) * 3 * LW,
                            sizeof(float) * 3 * LW,
                            cudaMemcpyDeviceToDevice, s1);

    // Chain for grid 0 on the default stream.
    spconv_kernel<true,  false><<<HGRID, TPB>>>(feats0, nbr0, 0 * LW,  nullptr, bufA0);
    spconv_kernel<true,  false><<<HGRID, TPB>>>(bufA0,  nbr0, 1 * LW,  nullptr, bufB0);
    spconv_kernel<false, true ><<<HGRID, TPB>>>(bufB0,  nbr0, 2 * LW,  feats0,  out);

    // Chain for grid 1 on s1.
    spconv_kernel<true,  false><<<HGRID, TPB, 0, s1>>>(feats1, nbr1, 3 * LW, nullptr, bufA1);
    spconv_kernel<true,  false><<<HGRID, TPB, 0, s1>>>(bufA1,  nbr1, 4 * LW, nullptr, bufB1);
    spconv_kernel<false, true ><<<HGRID, TPB, 0, s1>>>(bufB1,  nbr1, 5 * LW, feats1,
                                                       out + (size_t)NVOX * CH);

    // Join: default stream waits for s1's chain.
    cudaEventRecord(eJoin, s1);
    cudaStreamWaitEvent(0, eJoin, 0);
}